// round 4
// baseline (speedup 1.0000x reference)
#include <cuda_runtime.h>

// RotatedNMSLayer, bitmask formulation:
//   A: sigmoid -> compact valid -> bitonic sort (conf desc, idx asc) -> gather
//   B: pairwise IoU suppression bitmask (upper triangle), whole chip
//   C: single-warp serial greedy scan over bitmask + output emit
//
// NUM_CLASSES==1 => class offset is identically 0, obx == boxes, cls == 0.

#define NMAX    5376
#define WORDS   84          // NMAX / 64
#define THREADS 1024
#define IOU_THR 0.25f
#define D_PRE   8           // scan prefetch depth (power of 2)

typedef unsigned long long u64;

// Persistent scratch (zero-initialized once; B rewrites all words it ever
// writes on every replay; words left of a row's diagonal block are never
// written and stay 0, which the scan relies on).
__device__ u64    g_mask[(size_t)NMAX * WORDS];
__device__ float4 g_box[NMAX];
__device__ float  g_area[NMAX];
__device__ float  g_conf[NMAX];
__device__ float  g_ang[NMAX];
__device__ int    g_V;

// ---------------------------------------------------------------------------
// Kernel A: keys + sort + gather (single block)
// ---------------------------------------------------------------------------
extern __shared__ u64 s_keys[];   // up to 8192 entries = 64 KB

__global__ __launch_bounds__(THREADS, 1)
void nms_sort_kernel(const float* __restrict__ ps,   // pred_scores   (N,1)
                     const float* __restrict__ pb,   // pred_bboxes   (N,4)
                     const float* __restrict__ pa,   // pred_angles   (N,1)
                     const float* __restrict__ ap,   // anchor_points (N,2)
                     const float* __restrict__ st,   // stride_tensor (N,1)
                     const float* __restrict__ ct,   // conf_threshold(1,)
                     int N)
{
    __shared__ int s_cnt;
    const int tid = threadIdx.x;
    if (tid == 0) s_cnt = 0;
    __syncthreads();

    const float thr = ct[0];

    // compact valid candidates; key = (~conf_bits << 32) | idx so ascending
    // u64 sort == conf descending, index ascending on ties (JAX stable order)
    for (int i = tid; i < N; i += THREADS) {
        float x    = ps[i];
        float conf = 1.0f / (1.0f + expf(-x));      // conf in (0,1): sign bit 0
        if (conf >= thr) {
            unsigned u = ~(__float_as_uint(conf) | 0x80000000u);
            int slot = atomicAdd(&s_cnt, 1);
            s_keys[slot] = ((u64)u << 32) | (unsigned)i;
        }
    }
    __syncthreads();
    const int V = s_cnt;

    int npad = 1;
    while (npad < V) npad <<= 1;

    for (int i = V + tid; i < npad; i += THREADS)
        s_keys[i] = 0xFFFFFFFFFFFFFFFFULL;

    // bitonic sort, ascending, npad elements
    for (int k = 2; k <= npad; k <<= 1) {
        for (int j = k >> 1; j > 0; j >>= 1) {
            __syncthreads();
            for (int i = tid; i < npad; i += THREADS) {
                int ixj = i ^ j;
                if (ixj > i) {
                    u64 a = s_keys[i], b = s_keys[ixj];
                    bool up = ((i & k) == 0);
                    if ((a > b) == up) { s_keys[i] = b; s_keys[ixj] = a; }
                }
            }
        }
    }
    __syncthreads();

    // gather boxes in sorted order into global scratch
    for (int p = tid; p < V; p += THREADS) {
        u64 key = s_keys[p];
        int idx = (int)(key & 0xFFFFFFFFu);
        float conf = __uint_as_float((~(unsigned)(key >> 32)) & 0x7FFFFFFFu);
        float ax = ap[idx * 2 + 0];
        float ay = ap[idx * 2 + 1];
        float s  = st[idx];
        float l = pb[idx * 4 + 0], t = pb[idx * 4 + 1];
        float r = pb[idx * 4 + 2], b = pb[idx * 4 + 3];
        float x1 = (ax - l) * s, y1 = (ay - t) * s;
        float x2 = (ax + r) * s, y2 = (ay + b) * s;
        g_box[p]  = make_float4(x1, y1, x2, y2);
        g_area[p] = (x2 - x1) * (y2 - y1);
        g_conf[p] = conf;
        g_ang[p]  = pa[idx];
    }
    if (tid == 0) g_V = V;
}

// ---------------------------------------------------------------------------
// Kernel B: suppression bitmask, 64x64 tiles, upper triangle (many blocks)
// ---------------------------------------------------------------------------
__global__ void nms_mask_kernel()
{
    const int rb = blockIdx.y;      // row block
    const int cb = blockIdx.x;      // col block
    if (cb < rb) return;

    const int V = g_V;
    const int row0 = rb * 64;
    const int col0 = cb * 64;
    if (row0 >= V) return;

    __shared__ float4 s_cbox[64];
    __shared__ float  s_carea[64];

    const int t = threadIdx.x;
    const int c = col0 + t;
    if (c < V) { s_cbox[t] = g_box[c]; s_carea[t] = g_area[c]; }
    __syncthreads();

    const int i = row0 + t;
    if (i >= V) return;

    const float4 b  = g_box[i];
    const float  ai = g_area[i];
    const int jmax = min(64, V - col0);

    u64 word = 0;
    for (int jj = 0; jj < jmax; jj++) {
        int j = col0 + jj;
        if (j > i) {
            float4 cj = s_cbox[jj];
            float iw = fmaxf(fminf(b.z, cj.z) - fmaxf(b.x, cj.x), 0.0f);
            float ih = fmaxf(fminf(b.w, cj.w) - fmaxf(b.y, cj.y), 0.0f);
            float inter = iw * ih;
            float iou   = inter / (ai + s_carea[jj] - inter);  // NaN>thr==false
            if (iou > IOU_THR) word |= 1ULL << jj;
        }
    }
    g_mask[(size_t)i * WORDS + cb] = word;
}

// ---------------------------------------------------------------------------
// Kernel C: serial greedy scan (warp 0) + output emit (all threads)
// ---------------------------------------------------------------------------
__global__ __launch_bounds__(THREADS, 1)
void nms_scan_emit_kernel(float* __restrict__ out,
                          const int N)
{
    __shared__ unsigned char s_alive[NMAX];
    const int V   = g_V;
    const int tid = threadIdx.x;

    if (tid < 32) {
        const int lane = tid;
        const int w0 = lane, w1 = lane + 32, w2 = lane + 64;
        const bool h2 = (w2 < WORDS);

        u64 remv0 = 0, remv1 = 0, remv2 = 0;
        u64 pre0[D_PRE], pre1[D_PRE], pre2[D_PRE];

        #pragma unroll
        for (int d = 0; d < D_PRE; d++) {
            if (d < V) {
                size_t base = (size_t)d * WORDS;
                pre0[d] = g_mask[base + w0];
                pre1[d] = g_mask[base + w1];
                pre2[d] = h2 ? g_mask[base + w2] : 0ULL;
            }
        }

        for (int i = 0; i < V; i++) {
            int w = i >> 6;                      // word containing bit i
            u64 v = (w < 32) ? remv0 : ((w < 64) ? remv1 : remv2);
            u64 word = __shfl_sync(0xFFFFFFFFu, v, w & 31);
            bool kept = ((word >> (i & 63)) & 1ULL) == 0ULL;

            int slot = i & (D_PRE - 1);
            if (kept) {
                remv0 |= pre0[slot];
                remv1 |= pre1[slot];
                remv2 |= pre2[slot];
            }
            if (lane == 0) s_alive[i] = kept;

            int nr = i + D_PRE;                  // prefetch row nr
            if (nr < V) {
                size_t base = (size_t)nr * WORDS;
                pre0[slot] = g_mask[base + w0];
                pre1[slot] = g_mask[base + w1];
                pre2[slot] = h2 ? g_mask[base + w2] : 0ULL;
            }
        }
    }
    __syncthreads();

    // emit output rows (zeros where not kept; covers the whole buffer)
    for (int p = tid; p < N; p += THREADS) {
        float o0 = 0.f, o1 = 0.f, o2 = 0.f, o3 = 0.f, o4 = 0.f, o5 = 0.f;
        if (p < V && s_alive[p]) {
            float4 b = g_box[p];
            o0 = b.x; o1 = b.y; o2 = b.z; o3 = b.w;
            o4 = g_ang[p];
            o5 = g_conf[p];
        }
        float* o = out + (size_t)p * 7;
        o[0] = o0; o[1] = o1; o[2] = o2; o[3] = o3;
        o[4] = o4; o[5] = o5; o[6] = 0.0f;       // cls == 0 (NUM_CLASSES == 1)
    }
}

// ---------------------------------------------------------------------------
extern "C" void kernel_launch(void* const* d_in, const int* in_sizes, int n_in,
                              void* d_out, int out_size)
{
    const float* ps = (const float*)d_in[0];   // pred_scores
    const float* pb = (const float*)d_in[1];   // pred_bboxes
    const float* pa = (const float*)d_in[2];   // pred_angles
    const float* ap = (const float*)d_in[3];   // anchor_points
    const float* st = (const float*)d_in[4];   // stride_tensor
    const float* ct = (const float*)d_in[5];   // conf_threshold

    const int N = in_sizes[0];                 // 5376

    const int smem_keys = NMAX <= 4096 ? 4096 * 8 : 8192 * 8;  // 64 KB worst case
    static bool attr_set = false;
    if (!attr_set) {
        cudaFuncSetAttribute(nms_sort_kernel,
                             cudaFuncAttributeMaxDynamicSharedMemorySize, smem_keys);
        attr_set = true;
    }

    nms_sort_kernel<<<1, THREADS, smem_keys>>>(ps, pb, pa, ap, st, ct, N);

    dim3 gridB(WORDS, WORDS);                  // 84 x 84, upper triangle active
    nms_mask_kernel<<<gridB, 64>>>();

    nms_scan_emit_kernel<<<1, THREADS>>>((float*)d_out, N);
}